// round 2
// baseline (speedup 1.0000x reference)
#include <cuda_runtime.h>
#include <cuda_bf16.h>
#include <math.h>

// ---------------------------------------------------------------------------
// Problem constants
// ---------------------------------------------------------------------------
#define B_   512
#define T_   100
#define X_   38
#define Z_   3
#define H_   500
#define G_   1500      // 3*H
#define L_   20
#define BT_  51200     // B*T

// Output layout: tuple flattened in reference order
#define OFF_XMU   0u
#define OFF_XSTD  1945600u   // BT*38
#define OFF_ZGEN  3891200u
#define OFF_ZFIN  4044800u
#define OFF_ZMU   4198400u
#define OFF_ZSTD  4352000u
#define OFF_LDJ   4505600u

// ---------------------------------------------------------------------------
// Scratch (device globals; no runtime allocation)
// ---------------------------------------------------------------------------
__device__ float g_gi[(size_t)BT_ * G_];    // [B,T,1500]  (reused enc then dec)
__device__ float g_h [(size_t)BT_ * H_];    // GRU raw output
__device__ float g_t1[(size_t)BT_ * H_];    // post-MLP intermediate
__device__ float g_hp[(size_t)BT_ * H_];    // post-MLP output
__device__ float g_whhT[(size_t)H_ * G_];   // transposed recurrent weights

// ---------------------------------------------------------------------------
// f32x2 helpers (packed fp32 FMA — ptxas never auto-fuses; full-rate FMA pipe)
// ---------------------------------------------------------------------------
typedef unsigned long long u64;

__device__ __forceinline__ u64 dup2(float x) {
    u64 r;
    unsigned xi = __float_as_uint(x);
    asm("mov.b64 %0, {%1,%2};" : "=l"(r) : "r"(xi), "r"(xi));
    return r;
}
__device__ __forceinline__ void fma2(u64& d, u64 a, u64 b) {
    asm("fma.rn.f32x2 %0, %1, %2, %0;" : "+l"(d) : "l"(a), "l"(b));
}
__device__ __forceinline__ void up2(u64 v, float& lo, float& hi) {
    unsigned l, h;
    asm("mov.b64 {%0,%1}, %2;" : "=r"(l), "=r"(h) : "l"(v));
    lo = __uint_as_float(l); hi = __uint_as_float(h);
}

__device__ __forceinline__ float softplusf(float x) {
    return (x > 20.f) ? x : log1pf(expf(x));
}
__device__ __forceinline__ float sigmoidf(float x) {
    return 1.f / (1.f + expf(-x));
}

// ---------------------------------------------------------------------------
// Transpose: in[R][C] -> out[C][R]
// ---------------------------------------------------------------------------
__global__ void transpose_kernel(const float* __restrict__ in, float* __restrict__ out,
                                 int R, int C) {
    __shared__ float tile[32][33];
    int c0 = blockIdx.x * 32, r0 = blockIdx.y * 32;
    int tx = threadIdx.x, ty = threadIdx.y;  // 32 x 8
    for (int i = ty; i < 32; i += 8) {
        int r = r0 + i, c = c0 + tx;
        tile[i][tx] = (r < R && c < C) ? in[(size_t)r * C + c] : 0.f;
    }
    __syncthreads();
    for (int i = ty; i < 32; i += 8) {
        int c = c0 + i, r = r0 + tx;
        if (c < C && r < R) out[(size_t)c * R + r] = tile[tx][i];
    }
}

// ---------------------------------------------------------------------------
// Generic GEMM:  C[M,N] = act(A[M,K] @ W[N,K]^T + bias[N])
// BM=BN=128, BK=8, 256 threads, 8x8 per thread, f32x2 accumulation.
// ACT: 0 = none, 1 = leaky_relu(0.1), 2 = softplus + 1e-4
// ---------------------------------------------------------------------------
template<int ACT>
__device__ __forceinline__ float epi(float v) {
    if (ACT == 1) return v > 0.f ? v : 0.1f * v;
    if (ACT == 2) return softplusf(v) + 1e-4f;
    return v;
}

template<int ACT>
__global__ __launch_bounds__(256) void gemm_bias_act(
    const float* __restrict__ A, const float* __restrict__ W,
    const float* __restrict__ bias, float* __restrict__ C,
    int M, int N, int K)
{
    __shared__ __align__(16) float As[8][128];
    __shared__ __align__(16) float Ws[8][128];
    const int tid = threadIdx.x;
    const int m0 = blockIdx.x * 128;
    const int n0 = blockIdx.y * 128;
    const int tx = tid & 15, ty = tid >> 4;

    u64 acc[8][4];
#pragma unroll
    for (int i = 0; i < 8; i++)
#pragma unroll
        for (int j = 0; j < 4; j++) acc[i][j] = 0ULL;

    for (int k0 = 0; k0 < K; k0 += 8) {
#pragma unroll
        for (int l = 0; l < 4; l++) {
            int i = tid + l * 256;            // 0..1023
            int m = i >> 3, k = i & 7;
            float va = 0.f, vw = 0.f;
            if (k0 + k < K)                 va = A[(size_t)(m0 + m) * K + (k0 + k)];
            if (k0 + k < K && n0 + m < N)   vw = W[(size_t)(n0 + m) * K + (k0 + k)];
            As[k][m] = va;
            Ws[k][m] = vw;
        }
        __syncthreads();
#pragma unroll
        for (int kk = 0; kk < 8; kk++) {
            float4 a0 = *(const float4*)&As[kk][ty * 8];
            float4 a1 = *(const float4*)&As[kk][ty * 8 + 4];
            const longlong2* wp = (const longlong2*)&Ws[kk][tx * 8];
            longlong2 bA = wp[0], bB = wp[1];
            u64 ad[8] = { dup2(a0.x), dup2(a0.y), dup2(a0.z), dup2(a0.w),
                          dup2(a1.x), dup2(a1.y), dup2(a1.z), dup2(a1.w) };
            u64 bp[4] = { (u64)bA.x, (u64)bA.y, (u64)bB.x, (u64)bB.y };
#pragma unroll
            for (int i = 0; i < 8; i++)
#pragma unroll
                for (int j = 0; j < 4; j++) fma2(acc[i][j], ad[i], bp[j]);
        }
        __syncthreads();
    }

#pragma unroll
    for (int i = 0; i < 8; i++) {
        size_t m = (size_t)(m0 + ty * 8 + i);
        float* crow = C + m * (size_t)N;
#pragma unroll
        for (int jp = 0; jp < 4; jp++) {
            float c0v, c1v; up2(acc[i][jp], c0v, c1v);
            int n = n0 + tx * 8 + jp * 2;
            if (n < N)     crow[n]     = epi<ACT>(c0v + bias[n]);
            if (n + 1 < N) crow[n + 1] = epi<ACT>(c1v + bias[n + 1]);
        }
    }
}

// ---------------------------------------------------------------------------
// GRU recurrence (persistent, batch-parallel). 8 batch rows / CTA, 64 CTAs.
// Thread j owns gate triplet (j, j+500, j+1000); h lives in smem.
//   gi: [B,T,1500] precomputed input gates (+bih)
//   WhhT: [500][1500], bhh: [1500]
//   hout: [B,T,500]
// ---------------------------------------------------------------------------
#define MB 8
__global__ __launch_bounds__(512) void gru_kernel(
    const float* __restrict__ gi, const float* __restrict__ WhhT,
    const float* __restrict__ bhh, float* __restrict__ hout)
{
    __shared__ __align__(16) float h_s[H_ * MB];   // h_s[k*8 + m]
    const int tid = threadIdx.x;
    const int bbase = blockIdx.x * MB;
    for (int i = tid; i < H_ * MB; i += 512) h_s[i] = 0.f;
    const bool act = (tid < H_);
    const int j = tid;
    float br = 0.f, bz = 0.f, bn = 0.f;
    if (act) { br = bhh[j]; bz = bhh[j + H_]; bn = bhh[j + 2 * H_]; }
    __syncthreads();

    for (int t = 0; t < T_; t++) {
        u64 ar[4], az[4], an[4];
#pragma unroll
        for (int p = 0; p < 4; p++) { ar[p] = 0ULL; az[p] = 0ULL; an[p] = 0ULL; }

        if (act) {
            const float* wp = WhhT + j;
#pragma unroll 4
            for (int k = 0; k < H_; k++) {
                const longlong2* hp = (const longlong2*)&h_s[k * MB];
                longlong2 hA = hp[0];   // pairs (m0,m1),(m2,m3)
                longlong2 hB = hp[1];   // pairs (m4,m5),(m6,m7)
                u64 wr = dup2(wp[0]);
                u64 wz = dup2(wp[H_]);
                u64 wn = dup2(wp[2 * H_]);
                fma2(ar[0], (u64)hA.x, wr); fma2(ar[1], (u64)hA.y, wr);
                fma2(ar[2], (u64)hB.x, wr); fma2(ar[3], (u64)hB.y, wr);
                fma2(az[0], (u64)hA.x, wz); fma2(az[1], (u64)hA.y, wz);
                fma2(az[2], (u64)hB.x, wz); fma2(az[3], (u64)hB.y, wz);
                fma2(an[0], (u64)hA.x, wn); fma2(an[1], (u64)hA.y, wn);
                fma2(an[2], (u64)hB.x, wn); fma2(an[3], (u64)hB.y, wn);
                wp += G_;
            }
        }
        __syncthreads();
        if (act) {
            float fr[8], fz[8], fn[8];
#pragma unroll
            for (int p = 0; p < 4; p++) {
                up2(ar[p], fr[2 * p], fr[2 * p + 1]);
                up2(az[p], fz[2 * p], fz[2 * p + 1]);
                up2(an[p], fn[2 * p], fn[2 * p + 1]);
            }
#pragma unroll
            for (int m = 0; m < MB; m++) {
                size_t row = ((size_t)(bbase + m) * T_ + t) * G_;
                float r  = sigmoidf(gi[row + j]           + fr[m] + br);
                float zg = sigmoidf(gi[row + j + H_]      + fz[m] + bz);
                float n  = tanhf   (gi[row + j + 2 * H_]  + r * (fn[m] + bn));
                float hprev = h_s[j * MB + m];
                float hnew = (1.f - zg) * n + zg * hprev;
                h_s[j * MB + m] = hnew;
                hout[((size_t)(bbase + m) * T_ + t) * H_ + j] = hnew;
            }
        }
        __syncthreads();
    }
}

// ---------------------------------------------------------------------------
// Latent scan: sequential over T, one warp per batch element.
//   inp = concat(h[b,t,:], z_prev); mu = inp@zmW^T+zmb;
//   std = softplus(inp@zsW^T+zsb)+1e-4; z = mu + std*eps
// Writes z_gen / z_mu / z_std into d_out.
// ---------------------------------------------------------------------------
__global__ __launch_bounds__(128) void latent_kernel(
    const float* __restrict__ hp, const float* __restrict__ eps,
    const float* __restrict__ zmW, const float* __restrict__ zmb,
    const float* __restrict__ zsW, const float* __restrict__ zsb,
    float* __restrict__ out)
{
    __shared__ float s_m[3 * 503], s_s[3 * 503], s_mb[3], s_sb[3];
    const int tid = threadIdx.x;
    for (int i = tid; i < 3 * 503; i += 128) { s_m[i] = zmW[i]; s_s[i] = zsW[i]; }
    if (tid < 3) { s_mb[tid] = zmb[tid]; s_sb[tid] = zsb[tid]; }
    __syncthreads();

    const int warp = tid >> 5, lane = tid & 31;
    const int b = blockIdx.x * 4 + warp;
    if (b >= B_) return;

    float z0 = 0.f, z1 = 0.f, z2 = 0.f;
    float* zg = out + OFF_ZGEN;
    float* zm = out + OFF_ZMU;
    float* zs = out + OFF_ZSTD;

    for (int t = 0; t < T_; t++) {
        float m0 = 0.f, m1 = 0.f, m2 = 0.f, s0 = 0.f, s1 = 0.f, s2 = 0.f;
        const float* hrow = hp + ((size_t)b * T_ + t) * H_;
        for (int jj = lane; jj < 503; jj += 32) {
            float v = (jj < 500) ? hrow[jj] : (jj == 500 ? z0 : (jj == 501 ? z1 : z2));
            m0 += v * s_m[jj]; m1 += v * s_m[503 + jj]; m2 += v * s_m[1006 + jj];
            s0 += v * s_s[jj]; s1 += v * s_s[503 + jj]; s2 += v * s_s[1006 + jj];
        }
#pragma unroll
        for (int o = 16; o > 0; o >>= 1) {
            m0 += __shfl_xor_sync(0xffffffffu, m0, o);
            m1 += __shfl_xor_sync(0xffffffffu, m1, o);
            m2 += __shfl_xor_sync(0xffffffffu, m2, o);
            s0 += __shfl_xor_sync(0xffffffffu, s0, o);
            s1 += __shfl_xor_sync(0xffffffffu, s1, o);
            s2 += __shfl_xor_sync(0xffffffffu, s2, o);
        }
        m0 += s_mb[0]; m1 += s_mb[1]; m2 += s_mb[2];
        float st0 = softplusf(s0 + s_sb[0]) + 1e-4f;
        float st1 = softplusf(s1 + s_sb[1]) + 1e-4f;
        float st2 = softplusf(s2 + s_sb[2]) + 1e-4f;
        size_t er = ((size_t)b * T_ + t) * 3;
        float e0 = eps[er], e1 = eps[er + 1], e2 = eps[er + 2];
        z0 = m0 + st0 * e0; z1 = m1 + st1 * e1; z2 = m2 + st2 * e2;
        if (lane == 0) {
            zg[er] = z0; zg[er + 1] = z1; zg[er + 2] = z2;
            zm[er] = m0; zm[er + 1] = m1; zm[er + 2] = m2;
            zs[er] = st0; zs[er + 1] = st1; zs[er + 2] = st2;
        }
    }
}

// ---------------------------------------------------------------------------
// Planar flow stack: per-(b,t) independent; 20 layers sequential on z.
// Reads z_gen, writes z_fin + log_det_jac (all in d_out).
// ---------------------------------------------------------------------------
__global__ __launch_bounds__(256) void flow_kernel(
    const float* __restrict__ fw, const float* __restrict__ fb,
    const float* __restrict__ fu, float* __restrict__ out)
{
    __shared__ float sw[L_][3], su[L_][3], sb[L_], suw[L_];
    const int tid = threadIdx.x;
    if (tid < L_) {
        float w0 = fw[tid * 3], w1 = fw[tid * 3 + 1], w2 = fw[tid * 3 + 2];
        float u0 = fu[tid * 3], u1 = fu[tid * 3 + 1], u2 = fu[tid * 3 + 2];
        float wu = w0 * u0 + w1 * u1 + w2 * u2;
        float m = -1.f + softplusf(wu);
        float ww = w0 * w0 + w1 * w1 + w2 * w2 + 1e-7f;
        float c = (m - wu) / ww;
        float uh0 = u0 + c * w0, uh1 = u1 + c * w1, uh2 = u2 + c * w2;
        sw[tid][0] = w0; sw[tid][1] = w1; sw[tid][2] = w2;
        su[tid][0] = uh0; su[tid][1] = uh1; su[tid][2] = uh2;
        sb[tid] = fb[tid];
        suw[tid] = uh0 * w0 + uh1 * w1 + uh2 * w2;
    }
    __syncthreads();
    int idx = blockIdx.x * 256 + tid;
    if (idx >= BT_) return;
    const float* zg = out + OFF_ZGEN;
    float z0 = zg[idx * 3], z1 = zg[idx * 3 + 1], z2 = zg[idx * 3 + 2];
    float ld = 0.f;
#pragma unroll
    for (int l = 0; l < L_; l++) {
        float lin = z0 * sw[l][0] + z1 * sw[l][1] + z2 * sw[l][2] + sb[l];
        float th = tanhf(lin);
        z0 += su[l][0] * th; z1 += su[l][1] * th; z2 += su[l][2] * th;
        float det = 1.f + (1.f - th * th) * suw[l];
        ld += logf(fabsf(det) + 1e-7f);
    }
    float* zf = out + OFF_ZFIN;
    zf[idx * 3] = z0; zf[idx * 3 + 1] = z1; zf[idx * 3 + 2] = z2;
    out[OFF_LDJ + idx] = ld;
}

// ---------------------------------------------------------------------------
// Launch
// ---------------------------------------------------------------------------
extern "C" void kernel_launch(void* const* d_in, const int* in_sizes, int n_in,
                              void* d_out, int out_size) {
    (void)in_sizes; (void)n_in; (void)out_size;
    const float* x        = (const float*)d_in[0];
    const float* eps      = (const float*)d_in[1];
    const float* enc_Wih  = (const float*)d_in[2];
    const float* enc_Whh  = (const float*)d_in[3];
    const float* enc_bih  = (const float*)d_in[4];
    const float* enc_bhh  = (const float*)d_in[5];
    const float* enc_W1   = (const float*)d_in[6];
    const float* enc_b1   = (const float*)d_in[7];
    const float* enc_W2   = (const float*)d_in[8];
    const float* enc_b2   = (const float*)d_in[9];
    const float* zm_W     = (const float*)d_in[10];
    const float* zm_b     = (const float*)d_in[11];
    const float* zs_W     = (const float*)d_in[12];
    const float* zs_b     = (const float*)d_in[13];
    const float* flow_w   = (const float*)d_in[14];
    const float* flow_b   = (const float*)d_in[15];
    const float* flow_u   = (const float*)d_in[16];
    const float* dec_Wih  = (const float*)d_in[17];
    const float* dec_Whh  = (const float*)d_in[18];
    const float* dec_bih  = (const float*)d_in[19];
    const float* dec_bhh  = (const float*)d_in[20];
    const float* dec_W1   = (const float*)d_in[21];
    const float* dec_b1   = (const float*)d_in[22];
    const float* dec_W2   = (const float*)d_in[23];
    const float* dec_W2b  = (const float*)d_in[24];
    const float* xm_W     = (const float*)d_in[25];
    const float* xm_b     = (const float*)d_in[26];
    const float* xs_W     = (const float*)d_in[27];
    const float* xs_b     = (const float*)d_in[28];
    float* out = (float*)d_out;

    float *gi, *h, *t1, *hp, *whhT;
    cudaGetSymbolAddress((void**)&gi,   g_gi);
    cudaGetSymbolAddress((void**)&h,    g_h);
    cudaGetSymbolAddress((void**)&t1,   g_t1);
    cudaGetSymbolAddress((void**)&hp,   g_hp);
    cudaGetSymbolAddress((void**)&whhT, g_whhT);

    dim3 tb(32, 8);
    dim3 tg(16, 47);  // cols(500)/32, rows(1500)/32

    // ---- Encoder ----
    transpose_kernel<<<tg, tb>>>(enc_Whh, whhT, G_, H_);
    gemm_bias_act<0><<<dim3(400, 12), 256>>>(x, enc_Wih, enc_bih, gi, BT_, G_, X_);
    gru_kernel<<<64, 512>>>(gi, whhT, enc_bhh, h);
    gemm_bias_act<1><<<dim3(400, 4), 256>>>(h,  enc_W1, enc_b1, t1, BT_, H_, H_);
    gemm_bias_act<1><<<dim3(400, 4), 256>>>(t1, enc_W2, enc_b2, hp, BT_, H_, H_);

    // ---- Latent scan + flows ----
    latent_kernel<<<128, 128>>>(hp, eps, zm_W, zm_b, zs_W, zs_b, out);
    flow_kernel<<<200, 256>>>(flow_w, flow_b, flow_u, out);

    // ---- Decoder ----
    transpose_kernel<<<tg, tb>>>(dec_Whh, whhT, G_, H_);
    gemm_bias_act<0><<<dim3(400, 12), 256>>>(out + OFF_ZFIN, dec_Wih, dec_bih, gi, BT_, G_, Z_);
    gru_kernel<<<64, 512>>>(gi, whhT, dec_bhh, h);
    gemm_bias_act<1><<<dim3(400, 4), 256>>>(h,  dec_W1, dec_b1, t1, BT_, H_, H_);
    gemm_bias_act<1><<<dim3(400, 4), 256>>>(t1, dec_W2, dec_W2b, hp, BT_, H_, H_);

    // ---- Output heads ----
    gemm_bias_act<0><<<dim3(400, 1), 256>>>(hp, xm_W, xm_b, out + OFF_XMU,  BT_, X_, H_);
    gemm_bias_act<2><<<dim3(400, 1), 256>>>(hp, xs_W, xs_b, out + OFF_XSTD, BT_, X_, H_);
}